// round 3
// baseline (speedup 1.0000x reference)
#include <cuda_runtime.h>
#include <math.h>

// Problem constants
#define Bb   2
#define Ss   2048
#define Dd   512
#define Hh   8
#define DHh  64
#define DFFf 2048
#define Mrows (Bb * Ss)   // 4096

// ---------------- scratch (no allocation allowed) ----------------
__device__ float g_q[Mrows * Dd];
__device__ float g_k[Mrows * Dd];
__device__ float g_v[Mrows * Dd];
__device__ float g_ctx[Mrows * Dd];
__device__ float g_attn[Mrows * Dd];
__device__ float g_h[Mrows * Dd];
__device__ float g_ff1[(size_t)Mrows * DFFf];
__device__ float g_ff2[Mrows * Dd];

// ---------------------------------------------------------------------------
// GEMM: C[m,n] = sum_k A[m,k] * W[n,k] + bias[n]   (torch Linear semantics)
// BM=128, BN=64, BK=32, 256 threads, 8x4 microtile.
// Dims used here are always multiples of tile sizes -> no bounds checks.
// ---------------------------------------------------------------------------
template <bool RELU>
__global__ void __launch_bounds__(256) gemm_bias_kernel(
    const float* __restrict__ A, const float* __restrict__ W,
    const float* __restrict__ bias, float* __restrict__ C,
    int N, int K)
{
    constexpr int BM = 128, BN = 64, BK = 32, TM = 8, TN = 4;
    __shared__ float As[BM][BK + 1];
    __shared__ float Bs[BN][BK + 1];

    const int tid  = threadIdx.x;
    const int trow = tid >> 4;      // 0..15
    const int tcol = tid & 15;      // 0..15
    const int m0   = blockIdx.y * BM;
    const int n0   = blockIdx.x * BN;

    float acc[TM][TN];
#pragma unroll
    for (int i = 0; i < TM; i++)
#pragma unroll
        for (int j = 0; j < TN; j++) acc[i][j] = 0.f;

    for (int k0 = 0; k0 < K; k0 += BK) {
        // load A tile: 128x32 floats = 1024 float4, 4 per thread
#pragma unroll
        for (int r = 0; r < 4; ++r) {
            int f  = tid + 256 * r;
            int ar = f >> 3;
            int ac = (f & 7) << 2;
            const float4 val = *(const float4*)(A + (size_t)(m0 + ar) * K + k0 + ac);
            As[ar][ac]     = val.x;
            As[ar][ac + 1] = val.y;
            As[ar][ac + 2] = val.z;
            As[ar][ac + 3] = val.w;
        }
        // load W tile: 64x32 floats = 512 float4, 2 per thread
#pragma unroll
        for (int r = 0; r < 2; ++r) {
            int f  = tid + 256 * r;
            int br = f >> 3;
            int bc = (f & 7) << 2;
            const float4 val = *(const float4*)(W + (size_t)(n0 + br) * K + k0 + bc);
            Bs[br][bc]     = val.x;
            Bs[br][bc + 1] = val.y;
            Bs[br][bc + 2] = val.z;
            Bs[br][bc + 3] = val.w;
        }
        __syncthreads();

#pragma unroll
        for (int kk = 0; kk < BK; ++kk) {
            float a[TM], b[TN];
#pragma unroll
            for (int i = 0; i < TM; i++) a[i] = As[trow * TM + i][kk];
#pragma unroll
            for (int j = 0; j < TN; j++) b[j] = Bs[tcol * TN + j][kk];
#pragma unroll
            for (int i = 0; i < TM; i++)
#pragma unroll
                for (int j = 0; j < TN; j++)
                    acc[i][j] = fmaf(a[i], b[j], acc[i][j]);
        }
        __syncthreads();
    }

    float bj[TN];
#pragma unroll
    for (int j = 0; j < TN; j++) bj[j] = bias[n0 + tcol * TN + j];

#pragma unroll
    for (int i = 0; i < TM; i++) {
        size_t row = (size_t)(m0 + trow * TM + i) * N + n0 + tcol * TN;
#pragma unroll
        for (int j = 0; j < TN; j++) {
            float c = acc[i][j] + bj[j];
            if (RELU) c = fmaxf(c, 0.f);
            C[row + j] = c;
        }
    }
}

// ---------------------------------------------------------------------------
// Causal flash attention. grid = (S/64, B*H), 256 threads.
// Q/K/V in [B,S,D] layout (head h = cols h*64..h*64+63).
// Output ctx written back in [B,S,D] layout with head_alpha applied.
// Dynamic smem: Qs | KPs (K tile, reused as P tile) | Vs, each 64x65 floats.
// ---------------------------------------------------------------------------
__global__ void __launch_bounds__(256) attn_kernel(
    const float* __restrict__ q, const float* __restrict__ k,
    const float* __restrict__ v, const float* __restrict__ alphas,
    float* __restrict__ ctx)
{
    extern __shared__ float sm[];
    float (*Qs)[65]  = (float(*)[65])sm;
    float (*KPs)[65] = (float(*)[65])(sm + 64 * 65);
    float (*Vs)[65]  = (float(*)[65])(sm + 2 * 64 * 65);

    const int qt = blockIdx.x;          // query tile (64 rows)
    const int bh = blockIdx.y;
    const int b  = bh >> 3;
    const int h  = bh & 7;

    const size_t base = (size_t)b * Ss * Dd + (size_t)h * DHh;
    const float* qb = q + base;
    const float* kb = k + base;
    const float* vb = v + base;
    float* cb = ctx + base;

    const int tid  = threadIdx.x;
    const int trow = tid >> 4;   // 0..15 -> 4 query rows each
    const int tcol = tid & 15;   // 0..15 -> 4 cols each

    // load Q tile (64x64): 1024 float4, 4 per thread
#pragma unroll
    for (int r = 0; r < 4; ++r) {
        int f   = tid + 256 * r;
        int row = f >> 4;
        int c   = (f & 15) << 2;
        const float4 val = *(const float4*)(qb + (size_t)(qt * 64 + row) * Dd + c);
        Qs[row][c]     = val.x;
        Qs[row][c + 1] = val.y;
        Qs[row][c + 2] = val.z;
        Qs[row][c + 3] = val.w;
    }

    float m_i[4], l_i[4], acc[4][4];
#pragma unroll
    for (int i = 0; i < 4; i++) {
        m_i[i] = -1e30f;
        l_i[i] = 0.f;
#pragma unroll
        for (int j = 0; j < 4; j++) acc[i][j] = 0.f;
    }

    for (int kt = 0; kt <= qt; ++kt) {
        __syncthreads();   // prev PV reads done (also orders Q load on first iter)

        // load K tile and V tile
#pragma unroll
        for (int r = 0; r < 4; ++r) {
            int f   = tid + 256 * r;
            int row = f >> 4;
            int c   = (f & 15) << 2;
            size_t off = (size_t)(kt * 64 + row) * Dd + c;
            float4 kv = *(const float4*)(kb + off);
            KPs[row][c]     = kv.x;
            KPs[row][c + 1] = kv.y;
            KPs[row][c + 2] = kv.z;
            KPs[row][c + 3] = kv.w;
            float4 vv = *(const float4*)(vb + off);
            Vs[row][c]     = vv.x;
            Vs[row][c + 1] = vv.y;
            Vs[row][c + 2] = vv.z;
            Vs[row][c + 3] = vv.w;
        }
        __syncthreads();

        // S = Q @ K^T (64x64x64)
        float s[4][4];
#pragma unroll
        for (int i = 0; i < 4; i++)
#pragma unroll
            for (int j = 0; j < 4; j++) s[i][j] = 0.f;
#pragma unroll 8
        for (int d = 0; d < 64; ++d) {
            float a[4], bb[4];
#pragma unroll
            for (int i = 0; i < 4; i++) a[i] = Qs[trow * 4 + i][d];
#pragma unroll
            for (int j = 0; j < 4; j++) bb[j] = KPs[tcol * 4 + j][d];
#pragma unroll
            for (int i = 0; i < 4; i++)
#pragma unroll
                for (int j = 0; j < 4; j++)
                    s[i][j] = fmaf(a[i], bb[j], s[i][j]);
        }
        __syncthreads();   // everyone done reading K before P overwrites it

        // scale + causal mask + online softmax update
        const float scale = 0.125f;   // 1/sqrt(64)
        float mnew[4], alpha[4];
#pragma unroll
        for (int i = 0; i < 4; i++) {
            float rm = -1e30f;
#pragma unroll
            for (int j = 0; j < 4; j++) {
                s[i][j] *= scale;
                if (kt == qt && (tcol * 4 + j) > (trow * 4 + i)) s[i][j] = -1e30f;
                rm = fmaxf(rm, s[i][j]);
            }
#pragma unroll
            for (int off = 8; off > 0; off >>= 1)
                rm = fmaxf(rm, __shfl_xor_sync(0xffffffffu, rm, off));
            mnew[i]  = fmaxf(m_i[i], rm);
            alpha[i] = __expf(m_i[i] - mnew[i]);
            float rs = 0.f;
#pragma unroll
            for (int j = 0; j < 4; j++) {
                float p = __expf(s[i][j] - mnew[i]);
                s[i][j] = p;
                rs += p;
            }
#pragma unroll
            for (int off = 8; off > 0; off >>= 1)
                rs += __shfl_xor_sync(0xffffffffu, rs, off);
            l_i[i] = l_i[i] * alpha[i] + rs;
            m_i[i] = mnew[i];
#pragma unroll
            for (int j = 0; j < 4; j++) acc[i][j] *= alpha[i];
            // write P into the (dead) K tile
#pragma unroll
            for (int j = 0; j < 4; j++)
                KPs[trow * 4 + i][tcol * 4 + j] = s[i][j];
        }
        __syncthreads();

        // O += P @ V  (64x64x64); acc cols = head dims tcol*4..+3
#pragma unroll 8
        for (int jj = 0; jj < 64; ++jj) {
            float p[4], vv[4];
#pragma unroll
            for (int i = 0; i < 4; i++) p[i] = KPs[trow * 4 + i][jj];
#pragma unroll
            for (int d = 0; d < 4; d++) vv[d] = Vs[jj][tcol * 4 + d];
#pragma unroll
            for (int i = 0; i < 4; i++)
#pragma unroll
                for (int d = 0; d < 4; d++)
                    acc[i][d] = fmaf(p[i], vv[d], acc[i][d]);
        }
    }

    const float ah = alphas[h];
#pragma unroll
    for (int i = 0; i < 4; i++) {
        float inv = ah / l_i[i];
        size_t row = (size_t)(qt * 64 + trow * 4 + i) * Dd + tcol * 4;
#pragma unroll
        for (int d = 0; d < 4; d++)
            cb[row + d] = acc[i][d] * inv;
    }
}

// ---------------------------------------------------------------------------
// out = LayerNorm(A + R) * g + b   (one block per row of 512, 256 threads)
// ---------------------------------------------------------------------------
__global__ void __launch_bounds__(256) add_ln_kernel(
    const float* __restrict__ A, const float* __restrict__ R,
    const float* __restrict__ g, const float* __restrict__ be,
    float* __restrict__ out)
{
    const int row = blockIdx.x;
    const int tid = threadIdx.x;
    const size_t base = (size_t)row * Dd;

    float v0 = A[base + tid]       + R[base + tid];
    float v1 = A[base + tid + 256] + R[base + tid + 256];

    __shared__ float red[8];
    __shared__ float mean_s, rstd_s;

    float s = v0 + v1;
#pragma unroll
    for (int off = 16; off > 0; off >>= 1) s += __shfl_xor_sync(0xffffffffu, s, off);
    if ((tid & 31) == 0) red[tid >> 5] = s;
    __syncthreads();
    if (tid == 0) {
        float t = 0.f;
#pragma unroll
        for (int i = 0; i < 8; i++) t += red[i];
        mean_s = t * (1.0f / Dd);
    }
    __syncthreads();

    const float mean = mean_s;
    float d0 = v0 - mean, d1 = v1 - mean;
    float qq = d0 * d0 + d1 * d1;
#pragma unroll
    for (int off = 16; off > 0; off >>= 1) qq += __shfl_xor_sync(0xffffffffu, qq, off);
    if ((tid & 31) == 0) red[tid >> 5] = qq;
    __syncthreads();
    if (tid == 0) {
        float t = 0.f;
#pragma unroll
        for (int i = 0; i < 8; i++) t += red[i];
        rstd_s = rsqrtf(t * (1.0f / Dd) + 1e-5f);
    }
    __syncthreads();

    const float rstd = rstd_s;
    out[base + tid]       = d0 * rstd * g[tid]       + be[tid];
    out[base + tid + 256] = d1 * rstd * g[tid + 256] + be[tid + 256];
}

// ---------------------------------------------------------------------------
extern "C" void kernel_launch(void* const* d_in, const int* in_sizes, int n_in,
                              void* d_out, int out_size)
{
    const float* x      = (const float*)d_in[0];
    // d_in[1] = attn_mask  (equivalent to causal predicate; handled in-kernel)
    const float* Wq     = (const float*)d_in[2];
    const float* bq     = (const float*)d_in[3];
    const float* Wk     = (const float*)d_in[4];
    const float* bk     = (const float*)d_in[5];
    const float* Wv     = (const float*)d_in[6];
    const float* bv     = (const float*)d_in[7];
    const float* Wo     = (const float*)d_in[8];
    const float* bo     = (const float*)d_in[9];
    const float* alphas = (const float*)d_in[10];
    const float* ln1g   = (const float*)d_in[11];
    const float* ln1b   = (const float*)d_in[12];
    const float* W1     = (const float*)d_in[13];
    const float* b1     = (const float*)d_in[14];
    const float* W2     = (const float*)d_in[15];
    const float* b2     = (const float*)d_in[16];
    const float* ln2g   = (const float*)d_in[17];
    const float* ln2b   = (const float*)d_in[18];
    float* out = (float*)d_out;

    float *q, *k, *v, *ctx, *attn, *h, *ff1, *ff2;
    cudaGetSymbolAddress((void**)&q,    g_q);
    cudaGetSymbolAddress((void**)&k,    g_k);
    cudaGetSymbolAddress((void**)&v,    g_v);
    cudaGetSymbolAddress((void**)&ctx,  g_ctx);
    cudaGetSymbolAddress((void**)&attn, g_attn);
    cudaGetSymbolAddress((void**)&h,    g_h);
    cudaGetSymbolAddress((void**)&ff1,  g_ff1);
    cudaGetSymbolAddress((void**)&ff2,  g_ff2);

    const dim3 gProj(Dd / 64, Mrows / 128);     // (8, 32)
    const dim3 gFF1(DFFf / 64, Mrows / 128);    // (32, 32)
    const dim3 gFF2(Dd / 64, Mrows / 128);      // (8, 32)

    // QKV projections
    gemm_bias_kernel<false><<<gProj, 256>>>(x, Wq, bq, q, Dd, Dd);
    gemm_bias_kernel<false><<<gProj, 256>>>(x, Wk, bk, k, Dd, Dd);
    gemm_bias_kernel<false><<<gProj, 256>>>(x, Wv, bv, v, Dd, Dd);

    // causal flash attention (fused head_alpha + layout restore)
    const int attn_smem = 3 * 64 * 65 * (int)sizeof(float);  // 49,920 B
    static bool attr_set = false;
    cudaFuncSetAttribute(attn_kernel,
                         cudaFuncAttributeMaxDynamicSharedMemorySize, attn_smem);
    (void)attr_set;
    attn_kernel<<<dim3(Ss / 64, Bb * Hh), 256, attn_smem>>>(q, k, v, alphas, ctx);

    // output projection
    gemm_bias_kernel<false><<<gProj, 256>>>(ctx, Wo, bo, attn, Dd, Dd);

    // residual + LN1 -> h
    add_ln_kernel<<<Mrows, 256>>>(x, attn, ln1g, ln1b, h);

    // FFN
    gemm_bias_kernel<true ><<<gFF1, 256>>>(h,   W1, b1, ff1, DFFf, Dd);
    gemm_bias_kernel<false><<<gFF2, 256>>>(ff1, W2, b2, ff2, Dd, DFFf);

    // residual + LN2 -> output
    add_ln_kernel<<<Mrows, 256>>>(h, ff2, ln2g, ln2b, out);
}

// round 6
// speedup vs baseline: 1.2252x; 1.2252x over previous
#include <cuda_runtime.h>
#include <cstdint>
#include <math.h>

// Problem constants
#define Bb   2
#define Ss   2048
#define Dd   512
#define Hh   8
#define DHh  64
#define DFFf 2048
#define Mrows (Bb * Ss)   // 4096

// ---------------- scratch (no allocation allowed) ----------------
__device__ float g_q[Mrows * Dd];
__device__ float g_k[Mrows * Dd];
__device__ float g_v[Mrows * Dd];
__device__ float g_ctx[Mrows * Dd];
__device__ float g_attn[Mrows * Dd];
__device__ float g_h[Mrows * Dd];
__device__ float g_ff1[(size_t)Mrows * DFFf];
__device__ float g_ff2[Mrows * Dd];

// =========================== helpers ====================================
__device__ __forceinline__ uint32_t f2tf32(float f) {
    uint32_t r;
    asm("cvt.rna.tf32.f32 %0, %1;" : "=r"(r) : "f"(f));
    return r;
}

__device__ __forceinline__ void mma1688(float* c, const uint32_t* a, const uint32_t* b) {
    asm volatile(
        "mma.sync.aligned.m16n8k8.row.col.f32.tf32.tf32.f32 "
        "{%0,%1,%2,%3}, {%4,%5,%6,%7}, {%8,%9}, {%0,%1,%2,%3};"
        : "+f"(c[0]), "+f"(c[1]), "+f"(c[2]), "+f"(c[3])
        : "r"(a[0]), "r"(a[1]), "r"(a[2]), "r"(a[3]),
          "r"(b[0]), "r"(b[1]));
}

// ---------------------------------------------------------------------------
// tf32 mma.sync GEMM: C[m,n] = sum_k A[m,k] * W[n,k] + bias[n]
// CTA tile 128x128x32, 256 threads = 8 warps (4 rows x 2 cols),
// warp tile 32x64. Smem holds tiles PRE-SWIZZLED into mma fragment layout
// (tf32-converted), so the mainloop uses LDS.128/LDS.64 frag loads only.
// ---------------------------------------------------------------------------
template <bool RELU>
__global__ void __launch_bounds__(256)
tc_gemm_kernel(const float* __restrict__ A, const float* __restrict__ W,
               const float* __restrict__ bias, float* __restrict__ C,
               int N, int K)
{
    // [mtile 0..7][kstep 0..3][lane][reg]
    __shared__ alignas(16) uint32_t sA[8][4][32][4];   // 16 KB
    // [ntile 0..15][kstep 0..3][lane][reg]
    __shared__ alignas(16) uint32_t sB[16][4][32][2];  // 16 KB

    const int tid  = threadIdx.x;
    const int wid  = tid >> 5;
    const int lane = tid & 31;
    const int wrow = wid >> 1;          // 0..3
    const int wcol = wid & 1;           // 0..1
    const int m0   = blockIdx.y * 128;
    const int n0   = blockIdx.x * 128;

    const int g = lane >> 2;            // groupID
    const int t = lane & 3;             // thread in group

    float acc[2][8][4];
#pragma unroll
    for (int i = 0; i < 2; i++)
#pragma unroll
        for (int j = 0; j < 8; j++)
#pragma unroll
            for (int e = 0; e < 4; e++) acc[i][j][e] = 0.f;

    for (int k0 = 0; k0 < K; k0 += 32) {
        __syncthreads();   // previous iteration's frag reads done

        // ---- stage A tile (128x32) into fragment layout ----
#pragma unroll
        for (int it = 0; it < 4; ++it) {
            const int f  = tid + 256 * it;
            const int r  = f >> 3;           // 0..127
            const int c4 = f & 7;            // float4 index in row
            const float4 v = *(const float4*)(A + (size_t)(m0 + r) * K + k0 + c4 * 4);
            const int mt      = r >> 4;
            const int rr      = r & 15;
            const int ga      = rr & 7;
            const int rowhalf = rr >> 3;
            const int ks      = c4 >> 1;
            const int colhalf = c4 & 1;
            const int reg     = rowhalf + 2 * colhalf;
            uint32_t* dst = &sA[mt][ks][ga * 4][reg];
            dst[0 * 4] = f2tf32(v.x);
            dst[1 * 4] = f2tf32(v.y);
            dst[2 * 4] = f2tf32(v.z);
            dst[3 * 4] = f2tf32(v.w);
        }
        // ---- stage W tile (128x32) into B fragment layout ----
#pragma unroll
        for (int it = 0; it < 4; ++it) {
            const int f  = tid + 256 * it;
            const int r  = f >> 3;           // n row 0..127
            const int c4 = f & 7;
            const float4 v = *(const float4*)(W + (size_t)(n0 + r) * K + k0 + c4 * 4);
            const int nt  = r >> 3;
            const int gb  = r & 7;
            const int ks  = c4 >> 1;
            const int reg = c4 & 1;          // b0 (k<4) / b1 (k>=4)
            uint32_t* dst = &sB[nt][ks][gb * 4][reg];
            dst[0 * 2] = f2tf32(v.x);
            dst[1 * 2] = f2tf32(v.y);
            dst[2 * 2] = f2tf32(v.z);
            dst[3 * 2] = f2tf32(v.w);
        }
        __syncthreads();

        // ---- mainloop: frag loads + HMMA ----
#pragma unroll
        for (int ks = 0; ks < 4; ++ks) {
            uint32_t afr[2][4];
#pragma unroll
            for (int mt = 0; mt < 2; ++mt) {
                const uint4 va = *(const uint4*)sA[wrow * 2 + mt][ks][lane];
                afr[mt][0] = va.x; afr[mt][1] = va.y;
                afr[mt][2] = va.z; afr[mt][3] = va.w;
            }
            uint32_t bfr[8][2];
#pragma unroll
            for (int nt = 0; nt < 8; ++nt) {
                const uint2 vb = *(const uint2*)sB[wcol * 8 + nt][ks][lane];
                bfr[nt][0] = vb.x; bfr[nt][1] = vb.y;
            }
#pragma unroll
            for (int mt = 0; mt < 2; ++mt)
#pragma unroll
                for (int nt = 0; nt < 8; ++nt)
                    mma1688(acc[mt][nt], afr[mt], bfr[nt]);
        }
    }

    // ---- epilogue: bias (+ReLU), float2 stores ----
#pragma unroll
    for (int mt = 0; mt < 2; ++mt) {
        const int rbase = m0 + wrow * 32 + mt * 16;
#pragma unroll
        for (int nt = 0; nt < 8; ++nt) {
            const int cbase = n0 + wcol * 64 + nt * 8 + t * 2;
            const float b0 = bias[cbase];
            const float b1 = bias[cbase + 1];
            float2 o0, o1;
            o0.x = acc[mt][nt][0] + b0;  o0.y = acc[mt][nt][1] + b1;
            o1.x = acc[mt][nt][2] + b0;  o1.y = acc[mt][nt][3] + b1;
            if (RELU) {
                o0.x = fmaxf(o0.x, 0.f); o0.y = fmaxf(o0.y, 0.f);
                o1.x = fmaxf(o1.x, 0.f); o1.y = fmaxf(o1.y, 0.f);
            }
            *(float2*)(C + (size_t)(rbase + g)     * N + cbase) = o0;
            *(float2*)(C + (size_t)(rbase + g + 8) * N + cbase) = o1;
        }
    }
}

// ---------------------------------------------------------------------------
// Causal flash attention. grid = (S/64, B*H), 256 threads.
// ---------------------------------------------------------------------------
__global__ void __launch_bounds__(256, 4) attn_kernel(
    const float* __restrict__ q, const float* __restrict__ k,
    const float* __restrict__ v, const float* __restrict__ alphas,
    float* __restrict__ ctx)
{
    extern __shared__ float sm[];
    float (*Qs)[65]  = (float(*)[65])sm;
    float (*KPs)[65] = (float(*)[65])(sm + 64 * 65);
    float (*Vs)[65]  = (float(*)[65])(sm + 2 * 64 * 65);

    const int qt = blockIdx.x;
    const int bh = blockIdx.y;
    const int b  = bh >> 3;
    const int h  = bh & 7;

    const size_t base = (size_t)b * Ss * Dd + (size_t)h * DHh;
    const float* qb = q + base;
    const float* kb = k + base;
    const float* vb = v + base;
    float* cb = ctx + base;

    const int tid  = threadIdx.x;
    const int trow = tid >> 4;
    const int tcol = tid & 15;

#pragma unroll
    for (int r = 0; r < 4; ++r) {
        int f   = tid + 256 * r;
        int row = f >> 4;
        int c   = (f & 15) << 2;
        const float4 val = *(const float4*)(qb + (size_t)(qt * 64 + row) * Dd + c);
        Qs[row][c]     = val.x;
        Qs[row][c + 1] = val.y;
        Qs[row][c + 2] = val.z;
        Qs[row][c + 3] = val.w;
    }

    float m_i[4], l_i[4], acc[4][4];
#pragma unroll
    for (int i = 0; i < 4; i++) {
        m_i[i] = -1e30f;
        l_i[i] = 0.f;
#pragma unroll
        for (int j = 0; j < 4; j++) acc[i][j] = 0.f;
    }

    for (int kt = 0; kt <= qt; ++kt) {
        __syncthreads();

#pragma unroll
        for (int r = 0; r < 4; ++r) {
            int f   = tid + 256 * r;
            int row = f >> 4;
            int c   = (f & 15) << 2;
            size_t off = (size_t)(kt * 64 + row) * Dd + c;
            float4 kv = *(const float4*)(kb + off);
            KPs[row][c]     = kv.x;
            KPs[row][c + 1] = kv.y;
            KPs[row][c + 2] = kv.z;
            KPs[row][c + 3] = kv.w;
            float4 vv = *(const float4*)(vb + off);
            Vs[row][c]     = vv.x;
            Vs[row][c + 1] = vv.y;
            Vs[row][c + 2] = vv.z;
            Vs[row][c + 3] = vv.w;
        }
        __syncthreads();

        float s[4][4];
#pragma unroll
        for (int i = 0; i < 4; i++)
#pragma unroll
            for (int j = 0; j < 4; j++) s[i][j] = 0.f;
#pragma unroll 8
        for (int d = 0; d < 64; ++d) {
            float a[4], bbv[4];
#pragma unroll
            for (int i = 0; i < 4; i++) a[i] = Qs[trow * 4 + i][d];
#pragma unroll
            for (int j = 0; j < 4; j++) bbv[j] = KPs[tcol * 4 + j][d];
#pragma unroll
            for (int i = 0; i < 4; i++)
#pragma unroll
                for (int j = 0; j < 4; j++)
                    s[i][j] = fmaf(a[i], bbv[j], s[i][j]);
        }
        __syncthreads();

        const float scale = 0.125f;
        float mnew[4], alpha[4];
#pragma unroll
        for (int i = 0; i < 4; i++) {
            float rm = -1e30f;
#pragma unroll
            for (int j = 0; j < 4; j++) {
                s[i][j] *= scale;
                if (kt == qt && (tcol * 4 + j) > (trow * 4 + i)) s[i][j] = -1e30f;
                rm = fmaxf(rm, s[i][j]);
            }
#pragma unroll
            for (int off = 8; off > 0; off >>= 1)
                rm = fmaxf(rm, __shfl_xor_sync(0xffffffffu, rm, off));
            mnew[i]  = fmaxf(m_i[i], rm);
            alpha[i] = __expf(m_i[i] - mnew[i]);
            float rs = 0.f;
#pragma unroll
            for (int j = 0; j < 4; j++) {
                float p = __expf(s[i][j] - mnew[i]);
                s[i][j] = p;
                rs += p;
            }
#pragma unroll
            for (int off = 8; off > 0; off >>= 1)
                rs += __shfl_xor_sync(0xffffffffu, rs, off);
            l_i[i] = l_i[i] * alpha[i] + rs;
            m_i[i] = mnew[i];
#pragma unroll
            for (int j = 0; j < 4; j++) acc[i][j] *= alpha[i];
#pragma unroll
            for (int j = 0; j < 4; j++)
                KPs[trow * 4 + i][tcol * 4 + j] = s[i][j];
        }
        __syncthreads();

#pragma unroll 8
        for (int jj = 0; jj < 64; ++jj) {
            float p[4], vv[4];
#pragma unroll
            for (int i = 0; i < 4; i++) p[i] = KPs[trow * 4 + i][jj];
#pragma unroll
            for (int d = 0; d < 4; d++) vv[d] = Vs[jj][tcol * 4 + d];
#pragma unroll
            for (int i = 0; i < 4; i++)
#pragma unroll
                for (int d = 0; d < 4; d++)
                    acc[i][d] = fmaf(p[i], vv[d], acc[i][d]);
        }
    }

    const float ah = alphas[h];
#pragma unroll
    for (int i = 0; i < 4; i++) {
        float inv = ah / l_i[i];
        size_t row = (size_t)(qt * 64 + trow * 4 + i) * Dd + tcol * 4;
#pragma unroll
        for (int d = 0; d < 4; d++)
            cb[row + d] = acc[i][d] * inv;
    }
}

// ---------------------------------------------------------------------------
// out = LayerNorm(A + R) * g + b   (one block per row of 512, 256 threads)
// ---------------------------------------------------------------------------
__global__ void __launch_bounds__(256) add_ln_kernel(
    const float* __restrict__ A, const float* __restrict__ R,
    const float* __restrict__ g, const float* __restrict__ be,
    float* __restrict__ out)
{
    const int row = blockIdx.x;
    const int tid = threadIdx.x;
    const size_t base = (size_t)row * Dd;

    float v0 = A[base + tid]       + R[base + tid];
    float v1 = A[base + tid + 256] + R[base + tid + 256];

    __shared__ float red[8];
    __shared__ float mean_s, rstd_s;

    float s = v0 + v1;
#pragma unroll
    for (int off = 16; off > 0; off >>= 1) s += __shfl_xor_sync(0xffffffffu, s, off);
    if ((tid & 31) == 0) red[tid >> 5] = s;
    __syncthreads();
    if (tid == 0) {
        float tt = 0.f;
#pragma unroll
        for (int i = 0; i < 8; i++) tt += red[i];
        mean_s = tt * (1.0f / Dd);
    }
    __syncthreads();

    const float mean = mean_s;
    float d0 = v0 - mean, d1 = v1 - mean;
    float qq = d0 * d0 + d1 * d1;
#pragma unroll
    for (int off = 16; off > 0; off >>= 1) qq += __shfl_xor_sync(0xffffffffu, qq, off);
    if ((tid & 31) == 0) red[tid >> 5] = qq;
    __syncthreads();
    if (tid == 0) {
        float tt = 0.f;
#pragma unroll
        for (int i = 0; i < 8; i++) tt += red[i];
        rstd_s = rsqrtf(tt * (1.0f / Dd) + 1e-5f);
    }
    __syncthreads();

    const float rstd = rstd_s;
    out[base + tid]       = d0 * rstd * g[tid]       + be[tid];
    out[base + tid + 256] = d1 * rstd * g[tid + 256] + be[tid + 256];
}

// ---------------------------------------------------------------------------
extern "C" void kernel_launch(void* const* d_in, const int* in_sizes, int n_in,
                              void* d_out, int out_size)
{
    const float* x      = (const float*)d_in[0];
    // d_in[1] = attn_mask (equivalent to causal predicate; handled in-kernel)
    const float* Wq     = (const float*)d_in[2];
    const float* bq     = (const float*)d_in[3];
    const float* Wk     = (const float*)d_in[4];
    const float* bk     = (const float*)d_in[5];
    const float* Wv     = (const float*)d_in[6];
    const float* bv     = (const float*)d_in[7];
    const float* Wo     = (const float*)d_in[8];
    const float* bo     = (const float*)d_in[9];
    const float* alphas = (const float*)d_in[10];
    const float* ln1g   = (const float*)d_in[11];
    const float* ln1b   = (const float*)d_in[12];
    const float* W1     = (const float*)d_in[13];
    const float* b1     = (const float*)d_in[14];
    const float* W2     = (const float*)d_in[15];
    const float* b2     = (const float*)d_in[16];
    const float* ln2g   = (const float*)d_in[17];
    const float* ln2b   = (const float*)d_in[18];
    float* out = (float*)d_out;

    float *q, *k, *v, *ctx, *attn, *h, *ff1, *ff2;
    cudaGetSymbolAddress((void**)&q,    g_q);
    cudaGetSymbolAddress((void**)&k,    g_k);
    cudaGetSymbolAddress((void**)&v,    g_v);
    cudaGetSymbolAddress((void**)&ctx,  g_ctx);
    cudaGetSymbolAddress((void**)&attn, g_attn);
    cudaGetSymbolAddress((void**)&h,    g_h);
    cudaGetSymbolAddress((void**)&ff1,  g_ff1);
    cudaGetSymbolAddress((void**)&ff2,  g_ff2);

    const dim3 gProj(Dd / 128, Mrows / 128);    // (4, 32)
    const dim3 gFF1(DFFf / 128, Mrows / 128);   // (16, 32)
    const dim3 gFF2(Dd / 128, Mrows / 128);     // (4, 32)

    // QKV projections (tf32 mma.sync)
    tc_gemm_kernel<false><<<gProj, 256>>>(x, Wq, bq, q, Dd, Dd);
    tc_gemm_kernel<false><<<gProj, 256>>>(x, Wk, bk, k, Dd, Dd);
    tc_gemm_kernel<false><<<gProj, 256>>>(x, Wv, bv, v, Dd, Dd);

    // causal flash attention (fused head_alpha + layout restore)
    const int attn_smem = 3 * 64 * 65 * (int)sizeof(float);  // 49,920 B
    cudaFuncSetAttribute(attn_kernel,
                         cudaFuncAttributeMaxDynamicSharedMemorySize, attn_smem);
    attn_kernel<<<dim3(Ss / 64, Bb * Hh), 256, attn_smem>>>(q, k, v, alphas, ctx);

    // output projection
    tc_gemm_kernel<false><<<gProj, 256>>>(ctx, Wo, bo, attn, Dd, Dd);

    // residual + LN1 -> h
    add_ln_kernel<<<Mrows, 256>>>(x, attn, ln1g, ln1b, h);

    // FFN
    tc_gemm_kernel<true ><<<gFF1, 256>>>(h,   W1, b1, ff1, DFFf, Dd);
    tc_gemm_kernel<false><<<gFF2, 256>>>(ff1, W2, b2, ff2, Dd, DFFf);

    // residual + LN2 -> output
    add_ln_kernel<<<Mrows, 256>>>(h, ff2, ln2g, ln2b, out);
}

// round 8
// speedup vs baseline: 1.6542x; 1.3501x over previous
#include <cuda_runtime.h>
#include <cstdint>
#include <math.h>

// Problem constants
#define Bb   2
#define Ss   2048
#define Dd   512
#define Hh   8
#define DHh  64
#define DFFf 2048
#define Mrows (Bb * Ss)   // 4096

// ---------------- scratch (no allocation allowed) ----------------
__device__ float g_q[Mrows * Dd];
__device__ float g_k[Mrows * Dd];
__device__ float g_v[Mrows * Dd];
__device__ float g_ctx[Mrows * Dd];
__device__ float g_attn[Mrows * Dd];
__device__ float g_h[Mrows * Dd];
__device__ float g_ff1[(size_t)Mrows * DFFf];
__device__ float g_ff2[Mrows * Dd];

// =========================== helpers ====================================
__device__ __forceinline__ uint32_t f2tf32(float f) {
    uint32_t r;
    asm("cvt.rna.tf32.f32 %0, %1;" : "=r"(r) : "f"(f));
    return r;
}

__device__ __forceinline__ void mma1688(float* c, const uint32_t* a, const uint32_t* b) {
    asm volatile(
        "mma.sync.aligned.m16n8k8.row.col.f32.tf32.tf32.f32 "
        "{%0,%1,%2,%3}, {%4,%5,%6,%7}, {%8,%9}, {%0,%1,%2,%3};"
        : "+f"(c[0]), "+f"(c[1]), "+f"(c[2]), "+f"(c[3])
        : "r"(a[0]), "r"(a[1]), "r"(a[2]), "r"(a[3]),
          "r"(b[0]), "r"(b[1]));
}

// ---------------------------------------------------------------------------
// tf32 mma.sync GEMM: C[m,n] = sum_k A[m,k] * W[n,k] + bias[n]
// CTA tile 128x128x32, 256 threads = 8 warps (4 rows x 2 cols),
// warp tile 32x64. Smem holds tiles PRE-SWIZZLED into mma fragment layout.
// ---------------------------------------------------------------------------
template <bool RELU>
__global__ void __launch_bounds__(256)
tc_gemm_kernel(const float* __restrict__ A, const float* __restrict__ W,
               const float* __restrict__ bias, float* __restrict__ C,
               int N, int K)
{
    __shared__ alignas(16) uint32_t sA[8][4][32][4];   // 16 KB
    __shared__ alignas(16) uint32_t sB[16][4][32][2];  // 16 KB

    const int tid  = threadIdx.x;
    const int wid  = tid >> 5;
    const int lane = tid & 31;
    const int wrow = wid >> 1;
    const int wcol = wid & 1;
    const int m0   = blockIdx.y * 128;
    const int n0   = blockIdx.x * 128;

    const int g = lane >> 2;
    const int t = lane & 3;

    float acc[2][8][4];
#pragma unroll
    for (int i = 0; i < 2; i++)
#pragma unroll
        for (int j = 0; j < 8; j++)
#pragma unroll
            for (int e = 0; e < 4; e++) acc[i][j][e] = 0.f;

    for (int k0 = 0; k0 < K; k0 += 32) {
        __syncthreads();

#pragma unroll
        for (int it = 0; it < 4; ++it) {
            const int f  = tid + 256 * it;
            const int r  = f >> 3;
            const int c4 = f & 7;
            const float4 v = *(const float4*)(A + (size_t)(m0 + r) * K + k0 + c4 * 4);
            const int mt      = r >> 4;
            const int rr      = r & 15;
            const int ga      = rr & 7;
            const int rowhalf = rr >> 3;
            const int ks      = c4 >> 1;
            const int colhalf = c4 & 1;
            const int reg     = rowhalf + 2 * colhalf;
            uint32_t* dst = &sA[mt][ks][ga * 4][reg];
            dst[0 * 4] = f2tf32(v.x);
            dst[1 * 4] = f2tf32(v.y);
            dst[2 * 4] = f2tf32(v.z);
            dst[3 * 4] = f2tf32(v.w);
        }
#pragma unroll
        for (int it = 0; it < 4; ++it) {
            const int f  = tid + 256 * it;
            const int r  = f >> 3;
            const int c4 = f & 7;
            const float4 v = *(const float4*)(W + (size_t)(n0 + r) * K + k0 + c4 * 4);
            const int nt  = r >> 3;
            const int gb  = r & 7;
            const int ks  = c4 >> 1;
            const int reg = c4 & 1;
            uint32_t* dst = &sB[nt][ks][gb * 4][reg];
            dst[0 * 2] = f2tf32(v.x);
            dst[1 * 2] = f2tf32(v.y);
            dst[2 * 2] = f2tf32(v.z);
            dst[3 * 2] = f2tf32(v.w);
        }
        __syncthreads();

#pragma unroll
        for (int ks = 0; ks < 4; ++ks) {
            uint32_t afr[2][4];
#pragma unroll
            for (int mt = 0; mt < 2; ++mt) {
                const uint4 va = *(const uint4*)sA[wrow * 2 + mt][ks][lane];
                afr[mt][0] = va.x; afr[mt][1] = va.y;
                afr[mt][2] = va.z; afr[mt][3] = va.w;
            }
            uint32_t bfr[8][2];
#pragma unroll
            for (int nt = 0; nt < 8; ++nt) {
                const uint2 vb = *(const uint2*)sB[wcol * 8 + nt][ks][lane];
                bfr[nt][0] = vb.x; bfr[nt][1] = vb.y;
            }
#pragma unroll
            for (int mt = 0; mt < 2; ++mt)
#pragma unroll
                for (int nt = 0; nt < 8; ++nt)
                    mma1688(acc[mt][nt], afr[mt], bfr[nt]);
        }
    }

#pragma unroll
    for (int mt = 0; mt < 2; ++mt) {
        const int rbase = m0 + wrow * 32 + mt * 16;
#pragma unroll
        for (int nt = 0; nt < 8; ++nt) {
            const int cbase = n0 + wcol * 64 + nt * 8 + t * 2;
            const float b0 = bias[cbase];
            const float b1 = bias[cbase + 1];
            float2 o0, o1;
            o0.x = acc[mt][nt][0] + b0;  o0.y = acc[mt][nt][1] + b1;
            o1.x = acc[mt][nt][2] + b0;  o1.y = acc[mt][nt][3] + b1;
            if (RELU) {
                o0.x = fmaxf(o0.x, 0.f); o0.y = fmaxf(o0.y, 0.f);
                o1.x = fmaxf(o1.x, 0.f); o1.y = fmaxf(o1.y, 0.f);
            }
            *(float2*)(C + (size_t)(rbase + g)     * N + cbase) = o0;
            *(float2*)(C + (size_t)(rbase + g + 8) * N + cbase) = o1;
        }
    }
}

// ---------------------------------------------------------------------------
// Tensor-core causal flash attention (tf32 mma.sync).
// grid = (S/128, B*H), 256 threads = 8 warps; warp owns 16 q rows.
// Dynamic smem layout (uint32 units):
//   Qf [8w][8kc][32lane][4]      8192  (a-frags, staged once)
//   Kf [8kc][8nt][32lane][2]     4096  (b-frags for Q@K^T; nt = kpos tile)
//   Vf [8kc][8nt][32lane][2]     4096  (b-frags for P@V; kc = kpos, nt = dim)
//   Psm [8w][16][68] floats      8704  (warp-private P tile)
// ---------------------------------------------------------------------------
__global__ void __launch_bounds__(256, 2) attn_kernel(
    const float* __restrict__ q, const float* __restrict__ k,
    const float* __restrict__ v, const float* __restrict__ alphas,
    float* __restrict__ ctx)
{
    extern __shared__ uint32_t smu[];
    uint32_t* Qf  = smu;
    uint32_t* Kf  = smu + 8192;
    uint32_t* Vf  = smu + 12288;
    float*    Psm = (float*)(smu + 16384);

    const int qt = blockIdx.x;           // 128-row q tile
    const int bh = blockIdx.y;
    const int b  = bh >> 3;
    const int h  = bh & 7;

    const size_t base = (size_t)b * Ss * Dd + (size_t)h * DHh;
    const float* qb = q + base;
    const float* kb = k + base;
    const float* vb = v + base;
    float* cb = ctx + base;

    const int tid  = threadIdx.x;
    const int wid  = tid >> 5;
    const int lane = tid & 31;
    const int g    = lane >> 2;
    const int t    = lane & 3;

    // ---- stage Q tile (128x64) into a-frag layout ----
#pragma unroll
    for (int it = 0; it < 8; ++it) {
        const int f  = tid + 256 * it;
        const int r  = f >> 4;           // 0..127
        const int c4 = f & 15;           // float4 within 64-dim row
        const float4 v4 = *(const float4*)(qb + (size_t)(qt * 128 + r) * Dd + c4 * 4);
        const int w   = r >> 4;
        const int rr  = r & 15;
        const int gg  = rr & 7;
        const int rh  = rr >> 3;
        const int kc  = c4 >> 1;
        const int reg = rh + 2 * (c4 & 1);
        uint32_t* dst = &Qf[(((w * 8 + kc) * 32) + gg * 4) * 4 + reg];
        dst[0 * 4] = f2tf32(v4.x);
        dst[1 * 4] = f2tf32(v4.y);
        dst[2 * 4] = f2tf32(v4.z);
        dst[3 * 4] = f2tf32(v4.w);
    }

    float oacc[8][4];
#pragma unroll
    for (int nt = 0; nt < 8; ++nt)
#pragma unroll
        for (int e = 0; e < 4; ++e) oacc[nt][e] = 0.f;
    float m0 = -1e30f, m1 = -1e30f, l0 = 0.f, l1 = 0.f;

    const int myDiag = 2 * qt + (wid >> 2);
    const int rloc0  = (wid & 3) * 16 + g;   // row offset within diag tile
    const int nkt    = 2 * qt + 2;
    const float* Pw  = Psm + wid * 1088;
    float* PwW       = Psm + wid * 1088;

    for (int kt = 0; kt < nkt; ++kt) {
        __syncthreads();   // prior iter frag reads done (covers Q stage on iter 0)

        // ---- stage K and V tiles (64x64 each) into b-frag layouts ----
#pragma unroll
        for (int it = 0; it < 4; ++it) {
            const int f  = tid + 256 * it;
            const int r  = f >> 4;        // 0..63
            const int c4 = f & 15;
            const size_t goff = (size_t)(kt * 64 + r) * Dd + c4 * 4;
            const float4 kv = *(const float4*)(kb + goff);
            {   // K: n-role = kpos (r), k-role = dim
                const int gg = r & 7, nt = r >> 3, kc = c4 >> 1, reg = c4 & 1;
                uint32_t* dst = &Kf[((kc * 8 + nt) * 32 + gg * 4) * 2 + reg];
                dst[0] = f2tf32(kv.x); dst[2] = f2tf32(kv.y);
                dst[4] = f2tf32(kv.z); dst[6] = f2tf32(kv.w);
            }
            const float4 vv = *(const float4*)(vb + goff);
            {   // V: k-role = kpos (r), n-role = dim
                const int kc = r >> 3, tt = r & 7;
                const int tq = tt & 3, reg = tt >> 2;
                const int nt = c4 >> 1, gb = (c4 & 1) * 4;
                uint32_t* dst = &Vf[((kc * 8 + nt) * 32 + gb * 4 + tq) * 2 + reg];
                dst[0]  = f2tf32(vv.x); dst[8]  = f2tf32(vv.y);
                dst[16] = f2tf32(vv.z); dst[24] = f2tf32(vv.w);
            }
        }
        __syncthreads();

        if (kt > myDiag) continue;   // causal skip (barriers already done)

        // ---- S = Q @ K^T ----
        float sacc[8][4];
#pragma unroll
        for (int nt = 0; nt < 8; ++nt)
#pragma unroll
            for (int e = 0; e < 4; ++e) sacc[nt][e] = 0.f;
#pragma unroll
        for (int kc = 0; kc < 8; ++kc) {
            const uint4 aq4 = *(const uint4*)&Qf[((wid * 8 + kc) * 32 + lane) * 4];
            uint32_t aq[4] = {aq4.x, aq4.y, aq4.z, aq4.w};
#pragma unroll
            for (int nt = 0; nt < 8; ++nt) {
                const uint2 kb2 = *(const uint2*)&Kf[((kc * 8 + nt) * 32 + lane) * 2];
                uint32_t bf[2] = {kb2.x, kb2.y};
                mma1688(sacc[nt], aq, bf);
            }
        }

        // ---- softmax (register/shuffle only) ----
        const bool diag = (kt == myDiag);
        const float scale = 0.125f;
        float rm0 = -1e30f, rm1 = -1e30f;
#pragma unroll
        for (int nt = 0; nt < 8; ++nt) {
            const int jc = nt * 8 + 2 * t;
            float s0 = sacc[nt][0] * scale;
            float s1 = sacc[nt][1] * scale;
            float s2 = sacc[nt][2] * scale;
            float s3 = sacc[nt][3] * scale;
            if (diag) {
                if (jc     > rloc0)     s0 = -1e30f;
                if (jc + 1 > rloc0)     s1 = -1e30f;
                if (jc     > rloc0 + 8) s2 = -1e30f;
                if (jc + 1 > rloc0 + 8) s3 = -1e30f;
            }
            sacc[nt][0] = s0; sacc[nt][1] = s1;
            sacc[nt][2] = s2; sacc[nt][3] = s3;
            rm0 = fmaxf(rm0, fmaxf(s0, s1));
            rm1 = fmaxf(rm1, fmaxf(s2, s3));
        }
        rm0 = fmaxf(rm0, __shfl_xor_sync(0xffffffffu, rm0, 1));
        rm0 = fmaxf(rm0, __shfl_xor_sync(0xffffffffu, rm0, 2));
        rm1 = fmaxf(rm1, __shfl_xor_sync(0xffffffffu, rm1, 1));
        rm1 = fmaxf(rm1, __shfl_xor_sync(0xffffffffu, rm1, 2));

        const float mn0 = fmaxf(m0, rm0);
        const float mn1 = fmaxf(m1, rm1);
        const float al0 = __expf(m0 - mn0);
        const float al1 = __expf(m1 - mn1);
        float sum0 = 0.f, sum1 = 0.f;
#pragma unroll
        for (int nt = 0; nt < 8; ++nt) {
            const int jc = nt * 8 + 2 * t;
            const float p0 = __expf(sacc[nt][0] - mn0);
            const float p1 = __expf(sacc[nt][1] - mn0);
            const float p2 = __expf(sacc[nt][2] - mn1);
            const float p3 = __expf(sacc[nt][3] - mn1);
            sum0 += p0 + p1;
            sum1 += p2 + p3;
            *(float2*)(PwW + g * 68 + jc)       = make_float2(p0, p1);
            *(float2*)(PwW + (g + 8) * 68 + jc) = make_float2(p2, p3);
        }
        sum0 += __shfl_xor_sync(0xffffffffu, sum0, 1);
        sum0 += __shfl_xor_sync(0xffffffffu, sum0, 2);
        sum1 += __shfl_xor_sync(0xffffffffu, sum1, 1);
        sum1 += __shfl_xor_sync(0xffffffffu, sum1, 2);
        l0 = l0 * al0 + sum0;  m0 = mn0;
        l1 = l1 * al1 + sum1;  m1 = mn1;
#pragma unroll
        for (int nt = 0; nt < 8; ++nt) {
            oacc[nt][0] *= al0; oacc[nt][1] *= al0;
            oacc[nt][2] *= al1; oacc[nt][3] *= al1;
        }
        __syncwarp();

        // ---- O += P @ V ----
#pragma unroll
        for (int kc = 0; kc < 8; ++kc) {
            const int col = kc * 8 + t;
            uint32_t pa[4];
            pa[0] = f2tf32(Pw[g * 68 + col]);
            pa[1] = f2tf32(Pw[(g + 8) * 68 + col]);
            pa[2] = f2tf32(Pw[g * 68 + col + 4]);
            pa[3] = f2tf32(Pw[(g + 8) * 68 + col + 4]);
#pragma unroll
            for (int nt = 0; nt < 8; ++nt) {
                const uint2 vb2 = *(const uint2*)&Vf[((kc * 8 + nt) * 32 + lane) * 2];
                uint32_t bf[2] = {vb2.x, vb2.y};
                mma1688(oacc[nt], pa, bf);
            }
        }
        __syncwarp();   // P reads done before next iter's stores
    }

    // ---- epilogue: normalize + head alpha, write ctx ----
    const float ah  = alphas[h];
    const float iv0 = ah / l0;
    const float iv1 = ah / l1;
    const int gr0 = qt * 128 + wid * 16 + g;
#pragma unroll
    for (int nt = 0; nt < 8; ++nt) {
        const int d0 = nt * 8 + 2 * t;
        *(float2*)(cb + (size_t)gr0 * Dd + d0) =
            make_float2(oacc[nt][0] * iv0, oacc[nt][1] * iv0);
        *(float2*)(cb + (size_t)(gr0 + 8) * Dd + d0) =
            make_float2(oacc[nt][2] * iv1, oacc[nt][3] * iv1);
    }
}

// ---------------------------------------------------------------------------
// out = LayerNorm(A + R) * g + b   (one block per row of 512, 256 threads)
// ---------------------------------------------------------------------------
__global__ void __launch_bounds__(256) add_ln_kernel(
    const float* __restrict__ A, const float* __restrict__ R,
    const float* __restrict__ g, const float* __restrict__ be,
    float* __restrict__ out)
{
    const int row = blockIdx.x;
    const int tid = threadIdx.x;
    const size_t base = (size_t)row * Dd;

    float v0 = A[base + tid]       + R[base + tid];
    float v1 = A[base + tid + 256] + R[base + tid + 256];

    __shared__ float red[8];
    __shared__ float mean_s, rstd_s;

    float s = v0 + v1;
#pragma unroll
    for (int off = 16; off > 0; off >>= 1) s += __shfl_xor_sync(0xffffffffu, s, off);
    if ((tid & 31) == 0) red[tid >> 5] = s;
    __syncthreads();
    if (tid == 0) {
        float tt = 0.f;
#pragma unroll
        for (int i = 0; i < 8; i++) tt += red[i];
        mean_s = tt * (1.0f / Dd);
    }
    __syncthreads();

    const float mean = mean_s;
    float d0 = v0 - mean, d1 = v1 - mean;
    float qq = d0 * d0 + d1 * d1;
#pragma unroll
    for (int off = 16; off > 0; off >>= 1) qq += __shfl_xor_sync(0xffffffffu, qq, off);
    if ((tid & 31) == 0) red[tid >> 5] = qq;
    __syncthreads();
    if (tid == 0) {
        float tt = 0.f;
#pragma unroll
        for (int i = 0; i < 8; i++) tt += red[i];
        rstd_s = rsqrtf(tt * (1.0f / Dd) + 1e-5f);
    }
    __syncthreads();

    const float rstd = rstd_s;
    out[base + tid]       = d0 * rstd * g[tid]       + be[tid];
    out[base + tid + 256] = d1 * rstd * g[tid + 256] + be[tid + 256];
}

// ---------------------------------------------------------------------------
extern "C" void kernel_launch(void* const* d_in, const int* in_sizes, int n_in,
                              void* d_out, int out_size)
{
    const float* x      = (const float*)d_in[0];
    // d_in[1] = attn_mask (equivalent to causal predicate; handled in-kernel)
    const float* Wq     = (const float*)d_in[2];
    const float* bq     = (const float*)d_in[3];
    const float* Wk     = (const float*)d_in[4];
    const float* bk     = (const float*)d_in[5];
    const float* Wv     = (const float*)d_in[6];
    const float* bv     = (const float*)d_in[7];
    const float* Wo     = (const float*)d_in[8];
    const float* bo     = (const float*)d_in[9];
    const float* alphas = (const float*)d_in[10];
    const float* ln1g   = (const float*)d_in[11];
    const float* ln1b   = (const float*)d_in[12];
    const float* W1     = (const float*)d_in[13];
    const float* b1     = (const float*)d_in[14];
    const float* W2     = (const float*)d_in[15];
    const float* b2     = (const float*)d_in[16];
    const float* ln2g   = (const float*)d_in[17];
    const float* ln2b   = (const float*)d_in[18];
    float* out = (float*)d_out;

    float *q, *k, *v, *ctx, *attn, *h, *ff1, *ff2;
    cudaGetSymbolAddress((void**)&q,    g_q);
    cudaGetSymbolAddress((void**)&k,    g_k);
    cudaGetSymbolAddress((void**)&v,    g_v);
    cudaGetSymbolAddress((void**)&ctx,  g_ctx);
    cudaGetSymbolAddress((void**)&attn, g_attn);
    cudaGetSymbolAddress((void**)&h,    g_h);
    cudaGetSymbolAddress((void**)&ff1,  g_ff1);
    cudaGetSymbolAddress((void**)&ff2,  g_ff2);

    const dim3 gProj(Dd / 128, Mrows / 128);    // (4, 32)
    const dim3 gFF1(DFFf / 128, Mrows / 128);   // (16, 32)
    const dim3 gFF2(Dd / 128, Mrows / 128);     // (4, 32)

    // QKV projections (tf32 mma.sync)
    tc_gemm_kernel<false><<<gProj, 256>>>(x, Wq, bq, q, Dd, Dd);
    tc_gemm_kernel<false><<<gProj, 256>>>(x, Wk, bk, k, Dd, Dd);
    tc_gemm_kernel<false><<<gProj, 256>>>(x, Wv, bv, v, Dd, Dd);

    // tensor-core causal flash attention
    const int attn_smem = (8192 + 4096 + 4096 + 8704) * 4;  // 100,352 B
    cudaFuncSetAttribute(attn_kernel,
                         cudaFuncAttributeMaxDynamicSharedMemorySize, attn_smem);
    attn_kernel<<<dim3(Ss / 128, Bb * Hh), 256, attn_smem>>>(q, k, v, alphas, ctx);

    // output projection
    tc_gemm_kernel<false><<<gProj, 256>>>(ctx, Wo, bo, attn, Dd, Dd);

    // residual + LN1 -> h
    add_ln_kernel<<<Mrows, 256>>>(x, attn, ln1g, ln1b, h);

    // FFN
    tc_gemm_kernel<true ><<<gFF1, 256>>>(h,   W1, b1, ff1, DFFf, Dd);
    tc_gemm_kernel<false><<<gFF2, 256>>>(ff1, W2, b2, ff2, Dd, DFFf);

    // residual + LN2 -> output
    add_ln_kernel<<<Mrows, 256>>>(h, ff2, ln2g, ln2b, out);
}

// round 9
// speedup vs baseline: 1.8618x; 1.1255x over previous
#include <cuda_runtime.h>
#include <cstdint>
#include <math.h>

// Problem constants
#define Bb   2
#define Ss   2048
#define Dd   512
#define Hh   8
#define DHh  64
#define DFFf 2048
#define Mrows (Bb * Ss)   // 4096

// ---------------- scratch (no allocation allowed) ----------------
__device__ float g_q[Mrows * Dd];
__device__ float g_k[Mrows * Dd];
__device__ float g_v[Mrows * Dd];
__device__ float g_ctx[Mrows * Dd];
__device__ float g_attn[Mrows * Dd];
__device__ float g_h[Mrows * Dd];
__device__ float g_ff1[(size_t)Mrows * DFFf];
__device__ float g_ff2[Mrows * Dd];

// =========================== helpers ====================================
__device__ __forceinline__ void mma1688(float* c, const uint32_t* a, const uint32_t* b) {
    asm volatile(
        "mma.sync.aligned.m16n8k8.row.col.f32.tf32.tf32.f32 "
        "{%0,%1,%2,%3}, {%4,%5,%6,%7}, {%8,%9}, {%0,%1,%2,%3};"
        : "+f"(c[0]), "+f"(c[1]), "+f"(c[2]), "+f"(c[3])
        : "r"(a[0]), "r"(a[1]), "r"(a[2]), "r"(a[3]),
          "r"(b[0]), "r"(b[1]));
}

// ---------------------------------------------------------------------------
// tf32 mma.sync GEMM body: C[m,n] = sum_k A[m,k]*W[n,k] + bias[n]
// CTA tile 128x128x32, 256 thr = 8 warps (4x2), warp tile 32x64.
// DOUBLE-BUFFERED frag-layout smem (4 x 4096 u32 = 64KB dynamic) with
// register prefetch of chunk c+1 interleaved with the MMA phases of chunk c.
// Raw f32 bits fed to tf32 HMMA (HW truncates mantissa).
// ---------------------------------------------------------------------------
template <bool RELU>
__device__ __forceinline__ void gemm_body(
    const float* __restrict__ A, const float* __restrict__ W,
    const float* __restrict__ bias, float* __restrict__ C,
    int N, int K)
{
    extern __shared__ uint32_t smg[];
    uint32_t* sAb[2] = { smg,        smg + 4096 };
    uint32_t* sBb[2] = { smg + 8192, smg + 12288 };

    const int tid  = threadIdx.x;
    const int wid  = tid >> 5;
    const int lane = tid & 31;
    const int wrow = wid >> 1;
    const int wcol = wid & 1;
    const int m0   = blockIdx.y * 128;
    const int n0   = blockIdx.x * 128;
    const int g    = lane >> 2;
    const int t    = lane & 3;

    float acc[2][8][4];
#pragma unroll
    for (int i = 0; i < 2; i++)
#pragma unroll
        for (int j = 0; j < 8; j++)
#pragma unroll
            for (int e = 0; e < 4; e++) acc[i][j][e] = 0.f;

    // ---- staging / loading lambdas (identical index math to proven r6) ----
    auto loadA = [&](float4* p, int k0) {
#pragma unroll
        for (int it = 0; it < 4; ++it) {
            const int f = tid + 256 * it;
            const int r = f >> 3, c4 = f & 7;
            p[it] = *(const float4*)(A + (size_t)(m0 + r) * K + k0 + c4 * 4);
        }
    };
    auto loadB = [&](float4* p, int k0) {
#pragma unroll
        for (int it = 0; it < 4; ++it) {
            const int f = tid + 256 * it;
            const int r = f >> 3, c4 = f & 7;
            p[it] = *(const float4*)(W + (size_t)(n0 + r) * K + k0 + c4 * 4);
        }
    };
    auto stageA = [&](uint32_t* buf, const float4* p) {
#pragma unroll
        for (int it = 0; it < 4; ++it) {
            const int f = tid + 256 * it;
            const int r = f >> 3, c4 = f & 7;
            const int mt = r >> 4, rr = r & 15;
            const int ga = rr & 7, rh = rr >> 3;
            const int ks = c4 >> 1, ch = c4 & 1;
            const int reg = rh + 2 * ch;
            uint32_t* dst = buf + (((mt * 4 + ks) * 32) + ga * 4) * 4 + reg;
            dst[0 * 4] = __float_as_uint(p[it].x);
            dst[1 * 4] = __float_as_uint(p[it].y);
            dst[2 * 4] = __float_as_uint(p[it].z);
            dst[3 * 4] = __float_as_uint(p[it].w);
        }
    };
    auto stageB = [&](uint32_t* buf, const float4* p) {
#pragma unroll
        for (int it = 0; it < 4; ++it) {
            const int f = tid + 256 * it;
            const int r = f >> 3, c4 = f & 7;
            const int nt = r >> 3, gb = r & 7;
            const int ks = c4 >> 1, reg = c4 & 1;
            uint32_t* dst = buf + (((nt * 4 + ks) * 32) + gb * 4) * 2 + reg;
            dst[0 * 2] = __float_as_uint(p[it].x);
            dst[1 * 2] = __float_as_uint(p[it].y);
            dst[2 * 2] = __float_as_uint(p[it].z);
            dst[3 * 2] = __float_as_uint(p[it].w);
        }
    };
    auto compute2 = [&](const uint32_t* bufA, const uint32_t* bufB, int ks0) {
#pragma unroll
        for (int ks = ks0; ks < ks0 + 2; ++ks) {
            uint32_t afr[2][4];
#pragma unroll
            for (int mt = 0; mt < 2; ++mt) {
                const uint4 va = *(const uint4*)
                    (bufA + (((wrow * 2 + mt) * 4 + ks) * 32 + lane) * 4);
                afr[mt][0] = va.x; afr[mt][1] = va.y;
                afr[mt][2] = va.z; afr[mt][3] = va.w;
            }
            uint32_t bfr[8][2];
#pragma unroll
            for (int nt = 0; nt < 8; ++nt) {
                const uint2 vb = *(const uint2*)
                    (bufB + (((wcol * 8 + nt) * 4 + ks) * 32 + lane) * 2);
                bfr[nt][0] = vb.x; bfr[nt][1] = vb.y;
            }
#pragma unroll
            for (int mt = 0; mt < 2; ++mt)
#pragma unroll
                for (int nt = 0; nt < 8; ++nt)
                    mma1688(acc[mt][nt], afr[mt], bfr[nt]);
        }
    };

    // ---- prologue: stage chunk 0 into buffer 0 ----
    {
        float4 p[4];
        loadA(p, 0); stageA(sAb[0], p);
        loadB(p, 0); stageB(sBb[0], p);
    }
    __syncthreads();

    const int nc = K >> 5;
    for (int c = 0; c < nc; ++c) {
        const int nb = c & 1, fb = nb ^ 1;
        const bool nxt = (c + 1 < nc);
        const int k1 = (c + 1) << 5;

        float4 pre[4];
        if (nxt) loadA(pre, k1);          // LDGs issued before compute
        compute2(sAb[nb], sBb[nb], 0);
        if (nxt) stageA(sAb[fb], pre);
        if (nxt) loadB(pre, k1);
        compute2(sAb[nb], sBb[nb], 2);
        if (nxt) stageB(sBb[fb], pre);
        __syncthreads();
    }

    // ---- epilogue ----
#pragma unroll
    for (int mt = 0; mt < 2; ++mt) {
        const int rbase = m0 + wrow * 32 + mt * 16;
#pragma unroll
        for (int nt = 0; nt < 8; ++nt) {
            const int cbase = n0 + wcol * 64 + nt * 8 + t * 2;
            const float b0 = bias[cbase];
            const float b1 = bias[cbase + 1];
            float2 o0, o1;
            o0.x = acc[mt][nt][0] + b0;  o0.y = acc[mt][nt][1] + b1;
            o1.x = acc[mt][nt][2] + b0;  o1.y = acc[mt][nt][3] + b1;
            if (RELU) {
                o0.x = fmaxf(o0.x, 0.f); o0.y = fmaxf(o0.y, 0.f);
                o1.x = fmaxf(o1.x, 0.f); o1.y = fmaxf(o1.y, 0.f);
            }
            *(float2*)(C + (size_t)(rbase + g)     * N + cbase) = o0;
            *(float2*)(C + (size_t)(rbase + g + 8) * N + cbase) = o1;
        }
    }
}

template <bool RELU>
__global__ void __launch_bounds__(256)
tc_gemm_kernel(const float* __restrict__ A, const float* __restrict__ W,
               const float* __restrict__ bias, float* __restrict__ C,
               int N, int K)
{
    gemm_body<RELU>(A, W, bias, C, N, K);
}

// Merged QKV: grid.z selects {Wq,Wk,Wv} — fills the chip in one launch.
__global__ void __launch_bounds__(256)
qkv_kernel(const float* __restrict__ x,
           const float* __restrict__ Wq, const float* __restrict__ bq,
           const float* __restrict__ Wk, const float* __restrict__ bk,
           const float* __restrict__ Wv, const float* __restrict__ bv,
           float* __restrict__ q, float* __restrict__ k, float* __restrict__ v)
{
    const float* W; const float* bias; float* C;
    if (blockIdx.z == 0)      { W = Wq; bias = bq; C = q; }
    else if (blockIdx.z == 1) { W = Wk; bias = bk; C = k; }
    else                      { W = Wv; bias = bv; C = v; }
    gemm_body<false>(x, W, bias, C, Dd, Dd);
}

// ---------------------------------------------------------------------------
// Tensor-core causal flash attention (tf32 mma.sync).
// grid = (S/64, B*H), 128 threads = 4 warps; warp owns 16 q rows.
// Heavy tiles launched first (qt = 31 - blockIdx.x) for refill balance.
// Dynamic smem (u32): Qf 4096 | Kf 4096 | Vf 4096 | Psm 4x16x68 floats (4352)
// ---------------------------------------------------------------------------
__global__ void __launch_bounds__(128, 3) attn_kernel(
    const float* __restrict__ q, const float* __restrict__ k,
    const float* __restrict__ v, const float* __restrict__ alphas,
    float* __restrict__ ctx)
{
    extern __shared__ uint32_t smu[];
    uint32_t* Qf  = smu;
    uint32_t* Kf  = smu + 4096;
    uint32_t* Vf  = smu + 8192;
    float*    Psm = (float*)(smu + 12288);

    const int qt = (gridDim.x - 1) - blockIdx.x;   // heavy first
    const int bh = blockIdx.y;
    const int b  = bh >> 3;
    const int h  = bh & 7;

    const size_t base = (size_t)b * Ss * Dd + (size_t)h * DHh;
    const float* qb = q + base;
    const float* kb = k + base;
    const float* vb = v + base;
    float* cb = ctx + base;

    const int tid  = threadIdx.x;
    const int wid  = tid >> 5;
    const int lane = tid & 31;
    const int g    = lane >> 2;
    const int t    = lane & 3;

    // ---- stage Q tile (64x64) into a-frag layout ----
#pragma unroll
    for (int it = 0; it < 8; ++it) {
        const int f  = tid + 128 * it;
        const int r  = f >> 4;           // 0..63
        const int c4 = f & 15;
        const float4 v4 = *(const float4*)(qb + (size_t)(qt * 64 + r) * Dd + c4 * 4);
        const int w   = r >> 4;
        const int rr  = r & 15;
        const int gg  = rr & 7;
        const int rh  = rr >> 3;
        const int kc  = c4 >> 1;
        const int reg = rh + 2 * (c4 & 1);
        uint32_t* dst = &Qf[(((w * 8 + kc) * 32) + gg * 4) * 4 + reg];
        dst[0 * 4] = __float_as_uint(v4.x);
        dst[1 * 4] = __float_as_uint(v4.y);
        dst[2 * 4] = __float_as_uint(v4.z);
        dst[3 * 4] = __float_as_uint(v4.w);
    }

    float oacc[8][4];
#pragma unroll
    for (int nt = 0; nt < 8; ++nt)
#pragma unroll
        for (int e = 0; e < 4; ++e) oacc[nt][e] = 0.f;
    float m0 = -1e30f, m1 = -1e30f, l0 = 0.f, l1 = 0.f;

    const int rloc0 = wid * 16 + g;
    const int nkt   = qt + 1;
    const float* Pw = Psm + wid * 1088;
    float* PwW      = Psm + wid * 1088;

    for (int kt = 0; kt < nkt; ++kt) {
        __syncthreads();   // prior frag reads done (covers Q stage on iter 0)

        // ---- stage K and V tiles (64x64 each) into b-frag layouts ----
#pragma unroll
        for (int it = 0; it < 8; ++it) {
            const int f  = tid + 128 * it;
            const int r  = f >> 4;        // 0..63
            const int c4 = f & 15;
            const size_t goff = (size_t)(kt * 64 + r) * Dd + c4 * 4;
            const float4 kv = *(const float4*)(kb + goff);
            {   // K: n-role = kpos (r), k-role = dim
                const int gg = r & 7, nt = r >> 3, kc = c4 >> 1, reg = c4 & 1;
                uint32_t* dst = &Kf[((kc * 8 + nt) * 32 + gg * 4) * 2 + reg];
                dst[0] = __float_as_uint(kv.x); dst[2] = __float_as_uint(kv.y);
                dst[4] = __float_as_uint(kv.z); dst[6] = __float_as_uint(kv.w);
            }
            const float4 vv = *(const float4*)(vb + goff);
            {   // V: k-role = kpos (r), n-role = dim
                const int kc = r >> 3, tt = r & 7;
                const int tq = tt & 3, reg = tt >> 2;
                const int nt = c4 >> 1, gb = (c4 & 1) * 4;
                uint32_t* dst = &Vf[((kc * 8 + nt) * 32 + gb * 4 + tq) * 2 + reg];
                dst[0]  = __float_as_uint(vv.x); dst[8]  = __float_as_uint(vv.y);
                dst[16] = __float_as_uint(vv.z); dst[24] = __float_as_uint(vv.w);
            }
        }
        __syncthreads();

        // ---- S = Q @ K^T ----
        float sacc[8][4];
#pragma unroll
        for (int nt = 0; nt < 8; ++nt)
#pragma unroll
            for (int e = 0; e < 4; ++e) sacc[nt][e] = 0.f;
#pragma unroll
        for (int kc = 0; kc < 8; ++kc) {
            const uint4 aq4 = *(const uint4*)&Qf[((wid * 8 + kc) * 32 + lane) * 4];
            uint32_t aq[4] = {aq4.x, aq4.y, aq4.z, aq4.w};
#pragma unroll
            for (int nt = 0; nt < 8; ++nt) {
                const uint2 kb2 = *(const uint2*)&Kf[((kc * 8 + nt) * 32 + lane) * 2];
                uint32_t bf[2] = {kb2.x, kb2.y};
                mma1688(sacc[nt], aq, bf);
            }
        }

        // ---- softmax (register/shuffle only) ----
        const bool diag = (kt == qt);
        const float scale = 0.125f;
        float rm0 = -1e30f, rm1 = -1e30f;
#pragma unroll
        for (int nt = 0; nt < 8; ++nt) {
            const int jc = nt * 8 + 2 * t;
            float s0 = sacc[nt][0] * scale;
            float s1 = sacc[nt][1] * scale;
            float s2 = sacc[nt][2] * scale;
            float s3 = sacc[nt][3] * scale;
            if (diag) {
                if (jc     > rloc0)     s0 = -1e30f;
                if (jc + 1 > rloc0)     s1 = -1e30f;
                if (jc     > rloc0 + 8) s2 = -1e30f;
                if (jc + 1 > rloc0 + 8) s3 = -1e30f;
            }
            sacc[nt][0] = s0; sacc[nt][1] = s1;
            sacc[nt][2] = s2; sacc[nt][3] = s3;
            rm0 = fmaxf(rm0, fmaxf(s0, s1));
            rm1 = fmaxf(rm1, fmaxf(s2, s3));
        }
        rm0 = fmaxf(rm0, __shfl_xor_sync(0xffffffffu, rm0, 1));
        rm0 = fmaxf(rm0, __shfl_xor_sync(0xffffffffu, rm0, 2));
        rm1 = fmaxf(rm1, __shfl_xor_sync(0xffffffffu, rm1, 1));
        rm1 = fmaxf(rm1, __shfl_xor_sync(0xffffffffu, rm1, 2));

        const float mn0 = fmaxf(m0, rm0);
        const float mn1 = fmaxf(m1, rm1);
        const float al0 = __expf(m0 - mn0);
        const float al1 = __expf(m1 - mn1);
        float sum0 = 0.f, sum1 = 0.f;
#pragma unroll
        for (int nt = 0; nt < 8; ++nt) {
            const int jc = nt * 8 + 2 * t;
            const float p0 = __expf(sacc[nt][0] - mn0);
            const float p1 = __expf(sacc[nt][1] - mn0);
            const float p2 = __expf(sacc[nt][2] - mn1);
            const float p3 = __expf(sacc[nt][3] - mn1);
            sum0 += p0 + p1;
            sum1 += p2 + p3;
            *(float2*)(PwW + g * 68 + jc)       = make_float2(p0, p1);
            *(float2*)(PwW + (g + 8) * 68 + jc) = make_float2(p2, p3);
        }
        sum0 += __shfl_xor_sync(0xffffffffu, sum0, 1);
        sum0 += __shfl_xor_sync(0xffffffffu, sum0, 2);
        sum1 += __shfl_xor_sync(0xffffffffu, sum1, 1);
        sum1 += __shfl_xor_sync(0xffffffffu, sum1, 2);
        l0 = l0 * al0 + sum0;  m0 = mn0;
        l1 = l1 * al1 + sum1;  m1 = mn1;
#pragma unroll
        for (int nt = 0; nt < 8; ++nt) {
            oacc[nt][0] *= al0; oacc[nt][1] *= al0;
            oacc[nt][2] *= al1; oacc[nt][3] *= al1;
        }
        __syncwarp();

        // ---- O += P @ V ----
#pragma unroll
        for (int kc = 0; kc < 8; ++kc) {
            const int col = kc * 8 + t;
            uint32_t pa[4];
            pa[0] = __float_as_uint(Pw[g * 68 + col]);
            pa[1] = __float_as_uint(Pw[(g + 8) * 68 + col]);
            pa[2] = __float_as_uint(Pw[g * 68 + col + 4]);
            pa[3] = __float_as_uint(Pw[(g + 8) * 68 + col + 4]);
#pragma unroll
            for (int nt = 0; nt < 8; ++nt) {
                const uint2 vb2 = *(const uint2*)&Vf[((kc * 8 + nt) * 32 + lane) * 2];
                uint32_t bf[2] = {vb2.x, vb2.y};
                mma1688(oacc[nt], pa, bf);
            }
        }
        __syncwarp();   // P reads done before next iter's stores
    }

    // ---- epilogue: normalize + head alpha, write ctx ----
    const float ah  = alphas[h];
    const float iv0 = ah / l0;
    const float iv1 = ah / l1;
    const int gr0 = qt * 64 + wid * 16 + g;
#pragma unroll
    for (int nt = 0; nt < 8; ++nt) {
        const int d0 = nt * 8 + 2 * t;
        *(float2*)(cb + (size_t)gr0 * Dd + d0) =
            make_float2(oacc[nt][0] * iv0, oacc[nt][1] * iv0);
        *(float2*)(cb + (size_t)(gr0 + 8) * Dd + d0) =
            make_float2(oacc[nt][2] * iv1, oacc[nt][3] * iv1);
    }
}

// ---------------------------------------------------------------------------
// out = LayerNorm(A + R) * g + b   (one block per row of 512, 256 threads)
// ---------------------------------------------------------------------------
__global__ void __launch_bounds__(256) add_ln_kernel(
    const float* __restrict__ A, const float* __restrict__ R,
    const float* __restrict__ g, const float* __restrict__ be,
    float* __restrict__ out)
{
    const int row = blockIdx.x;
    const int tid = threadIdx.x;
    const size_t base = (size_t)row * Dd;

    float v0 = A[base + tid]       + R[base + tid];
    float v1 = A[base + tid + 256] + R[base + tid + 256];

    __shared__ float red[8];
    __shared__ float mean_s, rstd_s;

    float s = v0 + v1;
#pragma unroll
    for (int off = 16; off > 0; off >>= 1) s += __shfl_xor_sync(0xffffffffu, s, off);
    if ((tid & 31) == 0) red[tid >> 5] = s;
    __syncthreads();
    if (tid == 0) {
        float tt = 0.f;
#pragma unroll
        for (int i = 0; i < 8; i++) tt += red[i];
        mean_s = tt * (1.0f / Dd);
    }
    __syncthreads();

    const float mean = mean_s;
    float d0 = v0 - mean, d1 = v1 - mean;
    float qq = d0 * d0 + d1 * d1;
#pragma unroll
    for (int off = 16; off > 0; off >>= 1) qq += __shfl_xor_sync(0xffffffffu, qq, off);
    if ((tid & 31) == 0) red[tid >> 5] = qq;
    __syncthreads();
    if (tid == 0) {
        float tt = 0.f;
#pragma unroll
        for (int i = 0; i < 8; i++) tt += red[i];
        rstd_s = rsqrtf(tt * (1.0f / Dd) + 1e-5f);
    }
    __syncthreads();

    const float rstd = rstd_s;
    out[base + tid]       = d0 * rstd * g[tid]       + be[tid];
    out[base + tid + 256] = d1 * rstd * g[tid + 256] + be[tid + 256];
}

// ---------------------------------------------------------------------------
extern "C" void kernel_launch(void* const* d_in, const int* in_sizes, int n_in,
                              void* d_out, int out_size)
{
    const float* x      = (const float*)d_in[0];
    // d_in[1] = attn_mask (equivalent to causal predicate; handled in-kernel)
    const float* Wq     = (const float*)d_in[2];
    const float* bq     = (const float*)d_in[3];
    const float* Wk     = (const float*)d_in[4];
    const float* bk     = (const float*)d_in[5];
    const float* Wv     = (const float*)d_in[6];
    const float* bv     = (const float*)d_in[7];
    const float* Wo     = (const float*)d_in[8];
    const float* bo     = (const float*)d_in[9];
    const float* alphas = (const float*)d_in[10];
    const float* ln1g   = (const float*)d_in[11];
    const float* ln1b   = (const float*)d_in[12];
    const float* W1     = (const float*)d_in[13];
    const float* b1     = (const float*)d_in[14];
    const float* W2     = (const float*)d_in[15];
    const float* b2     = (const float*)d_in[16];
    const float* ln2g   = (const float*)d_in[17];
    const float* ln2b   = (const float*)d_in[18];
    float* out = (float*)d_out;

    float *q, *k, *v, *ctx, *attn, *h, *ff1, *ff2;
    cudaGetSymbolAddress((void**)&q,    g_q);
    cudaGetSymbolAddress((void**)&k,    g_k);
    cudaGetSymbolAddress((void**)&v,    g_v);
    cudaGetSymbolAddress((void**)&ctx,  g_ctx);
    cudaGetSymbolAddress((void**)&attn, g_attn);
    cudaGetSymbolAddress((void**)&h,    g_h);
    cudaGetSymbolAddress((void**)&ff1,  g_ff1);
    cudaGetSymbolAddress((void**)&ff2,  g_ff2);

    const int gemm_smem = 16384 * 4;                 // 64 KB
    const int attn_smem = (12288 + 4352) * 4;        // 66,560 B
    cudaFuncSetAttribute(qkv_kernel,
                         cudaFuncAttributeMaxDynamicSharedMemorySize, gemm_smem);
    cudaFuncSetAttribute(tc_gemm_kernel<false>,
                         cudaFuncAttributeMaxDynamicSharedMemorySize, gemm_smem);
    cudaFuncSetAttribute(tc_gemm_kernel<true>,
                         cudaFuncAttributeMaxDynamicSharedMemorySize, gemm_smem);
    cudaFuncSetAttribute(attn_kernel,
                         cudaFuncAttributeMaxDynamicSharedMemorySize, attn_smem);

    const dim3 gQKV(Dd / 128, Mrows / 128, 3);  // (4, 32, 3)
    const dim3 gProj(Dd / 128, Mrows / 128);    // (4, 32)
    const dim3 gFF1(DFFf / 128, Mrows / 128);   // (16, 32)
    const dim3 gFF2(Dd / 128, Mrows / 128);     // (4, 32)

    // QKV projections — single merged launch
    qkv_kernel<<<gQKV, 256, gemm_smem>>>(x, Wq, bq, Wk, bk, Wv, bv, q, k, v);

    // tensor-core causal flash attention
    attn_kernel<<<dim3(Ss / 64, Bb * Hh), 128, attn_smem>>>(q, k, v, alphas, ctx);

    // output projection
    tc_gemm_kernel<false><<<gProj, 256, gemm_smem>>>(ctx, Wo, bo, attn, Dd, Dd);

    // residual + LN1 -> h
    add_ln_kernel<<<Mrows, 256>>>(x, attn, ln1g, ln1b, h);

    // FFN
    tc_gemm_kernel<true ><<<gFF1, 256, gemm_smem>>>(h,   W1, b1, ff1, DFFf, Dd);
    tc_gemm_kernel<false><<<gFF2, 256, gemm_smem>>>(ff1, W2, b2, ff2, Dd, DFFf);

    // residual + LN2 -> output
    add_ln_kernel<<<Mrows, 256>>>(h, ff2, ln2g, ln2b, out);
}